// round 14
// baseline (speedup 1.0000x reference)
// FP8Linear on GB300 — R14: built on R13's GROUND-TRUTH dump.
// Facts: x = f32 (bf16 upcast), W = f32 of quantized fp8 values (OUT,IN),
// scale = f32[1], bias = f32 (bf16 upcast), out = f32 (harness marshals all
// to f32). Root cause of R2-R12: x misread as bf16 (junk A) every round.
// Pipeline: prep_x f32->bf16 | prep_w bf16(v)*bf16(scale) | validated HMMA
// GEMM (R5==R6) | epilogue out = f32( bf16(acc) +bf16 bf16(bias) ).
#include <cuda_runtime.h>
#include <cuda_bf16.h>
#include <cstdint>

static constexpr int K_DIM = 2048;
static constexpr int N_DIM = 2048;
static constexpr int M_DIM = 32768;   // 4 * 8192

static constexpr int BM = 128;
static constexpr int BN = 128;
static constexpr int BK = 64;            // 64 bf16 = 128 data bytes per row
static constexpr int STG = 3;
static constexpr int NKT = K_DIM / BK;   // 32

static constexpr int ROW_B   = 144;                   // padded row stride (bytes)
static constexpr int A_BYTES = BM * ROW_B;
static constexpr int B_BYTES = BN * ROW_B;
static constexpr int STAGE_BYTES = A_BYTES + B_BYTES;
static constexpr int SMEM_TOTAL = STG * STAGE_BYTES;  // 108 KB

// Scratch (allocation-free rule -> __device__ globals):
__device__ __nv_bfloat16 g_x[(size_t)M_DIM * K_DIM];   // 128 MB bf16 x
__device__ __nv_bfloat16 g_w[(size_t)N_DIM * K_DIM];   // 8 MB bf16 W

// ---------------- helpers ----------------
__device__ __forceinline__ uint32_t smem_u32(const void* p) {
    return (uint32_t)__cvta_generic_to_shared(p);
}
__device__ __forceinline__ void cp_async16(uint32_t dst, const void* src) {
    asm volatile("cp.async.cg.shared.global [%0], [%1], 16;"
                 :: "r"(dst), "l"(src) : "memory");
}
__device__ __forceinline__ void cp_commit() {
    asm volatile("cp.async.commit_group;" ::: "memory");
}
template <int N>
__device__ __forceinline__ void cp_wait() {
    asm volatile("cp.async.wait_group %0;" :: "n"(N) : "memory");
}
__device__ __forceinline__ void ldmatrix_x4(uint32_t* r, uint32_t addr) {
    asm volatile("ldmatrix.sync.aligned.m8n8.x4.shared.b16 {%0,%1,%2,%3}, [%4];"
                 : "=r"(r[0]), "=r"(r[1]), "=r"(r[2]), "=r"(r[3]) : "r"(addr));
}
__device__ __forceinline__ void mma_16816(float* c, const uint32_t* a,
                                          uint32_t b0, uint32_t b1) {
    asm volatile(
        "mma.sync.aligned.m16n8k16.row.col.f32.bf16.bf16.f32 "
        "{%0,%1,%2,%3}, {%4,%5,%6,%7}, {%8,%9}, {%0,%1,%2,%3};"
        : "+f"(c[0]), "+f"(c[1]), "+f"(c[2]), "+f"(c[3])
        : "r"(a[0]), "r"(a[1]), "r"(a[2]), "r"(a[3]), "r"(b0), "r"(b1));
}

// ---------------- Kernel 1a: x f32 -> bf16 (exact; bf16 upcast round-trips) --
__global__ void __launch_bounds__(256)
prep_x(const float* __restrict__ xf, __nv_bfloat16* __restrict__ xout) {
    const size_t i = (size_t)blockIdx.x * 256 + threadIdx.x;   // 8 elems/thread
    const float4* src = reinterpret_cast<const float4*>(xf) + 2 * i;
    float4 a = src[0], b = src[1];
    __nv_bfloat16 o[8];
    o[0] = __float2bfloat16(a.x); o[1] = __float2bfloat16(a.y);
    o[2] = __float2bfloat16(a.z); o[3] = __float2bfloat16(a.w);
    o[4] = __float2bfloat16(b.x); o[5] = __float2bfloat16(b.y);
    o[6] = __float2bfloat16(b.z); o[7] = __float2bfloat16(b.w);
    const uint32_t* op = reinterpret_cast<const uint32_t*>(o);
    reinterpret_cast<uint4*>(xout)[i] = make_uint4(op[0], op[1], op[2], op[3]);
}

// ---------------- Kernel 1b: W f32 quantized -> bf16(v) * bf16(scale) --------
__global__ void __launch_bounds__(256)
prep_w(const float* __restrict__ wf, const float* __restrict__ scale_p,
       __nv_bfloat16* __restrict__ wout) {
    const __nv_bfloat16 sb = __float2bfloat16(*scale_p);
    const size_t i = (size_t)blockIdx.x * 256 + threadIdx.x;   // 8 elems/thread
    const float4* src = reinterpret_cast<const float4*>(wf) + 2 * i;
    float4 a = src[0], b = src[1];
    float vv[8] = {a.x, a.y, a.z, a.w, b.x, b.y, b.z, b.w};
    __nv_bfloat16 o[8];
#pragma unroll
    for (int q = 0; q < 8; ++q)
        o[q] = __hmul(__float2bfloat16(vv[q]), sb);   // exact value, ref rounding
    const uint32_t* op = reinterpret_cast<const uint32_t*>(o);
    reinterpret_cast<uint4*>(wout)[i] = make_uint4(op[0], op[1], op[2], op[3]);
}

// ---------------- Kernel 2: HMMA bf16 GEMM -> f32 out ----------------
__global__ void __launch_bounds__(256, 1)
gemm_kernel(const __nv_bfloat16* __restrict__ x,
            const __nv_bfloat16* __restrict__ w,
            const float* __restrict__ bias,
            float* __restrict__ out) {
    extern __shared__ char smem[];
    const uint32_t sbase = smem_u32(smem);
    const int tid  = threadIdx.x;
    const int lane = tid & 31;
    const int wid  = tid >> 5;
    const int wm   = wid >> 1;     // 0..3 (M)
    const int wn   = wid & 1;      // 0..1 (N)
    const int m0   = blockIdx.y * BM;
    const int n0   = blockIdx.x * BN;

    const __nv_bfloat16* gA = x + (size_t)m0 * K_DIM;
    const __nv_bfloat16* gB = w + (size_t)n0 * K_DIM;

    auto load_stage = [&](int s, int kt) {
        const uint32_t aBase = sbase + s * STAGE_BYTES;
        const uint32_t bBase = aBase + A_BYTES;
        const int kOff = kt * BK;
#pragma unroll
        for (int i = 0; i < 4; ++i) {
            int c = tid + i * 256;
            int row = c >> 3, col = c & 7;
            cp_async16(aBase + row * ROW_B + col * 16,
                       gA + (size_t)row * K_DIM + kOff + col * 8);
        }
#pragma unroll
        for (int i = 0; i < 4; ++i) {
            int c = tid + i * 256;
            int row = c >> 3, col = c & 7;
            cp_async16(bBase + row * ROW_B + col * 16,
                       gB + (size_t)row * K_DIM + kOff + col * 8);
        }
        cp_commit();
    };

    float acc[2][8][4];
#pragma unroll
    for (int t = 0; t < 2; ++t)
#pragma unroll
        for (int j = 0; j < 8; ++j)
#pragma unroll
            for (int q = 0; q < 4; ++q) acc[t][j][q] = 0.f;

    const int aRow     = wm * 32 + (lane & 15);
    const int bRowBase = wn * 64 + (lane & 15);
    const int colHalf  = (lane >> 4) * 16;

    load_stage(0, 0);
    load_stage(1, 1);

    for (int kt = 0; kt < NKT; ++kt) {
        const int s = kt % STG;
        cp_wait<STG - 2>();
        __syncthreads();
        if (kt + STG - 1 < NKT) load_stage((kt + STG - 1) % STG, kt + STG - 1);

        const uint32_t aBase = sbase + s * STAGE_BYTES;
        const uint32_t bBase = aBase + A_BYTES;
#pragma unroll
        for (int kk = 0; kk < BK / 16; ++kk) {
            uint32_t af[2][4];
#pragma unroll
            for (int t = 0; t < 2; ++t)
                ldmatrix_x4(af[t], aBase + (aRow + t * 16) * ROW_B + kk * 32 + colHalf);
            uint32_t bf[4][4];
#pragma unroll
            for (int nt = 0; nt < 4; ++nt)
                ldmatrix_x4(bf[nt],
                            bBase + (bRowBase + nt * 16) * ROW_B + kk * 32 + colHalf);
#pragma unroll
            for (int t = 0; t < 2; ++t)
#pragma unroll
                for (int j = 0; j < 8; ++j) {
                    int nt = j >> 1, h = j & 1;
                    mma_16816(acc[t][j], af[t], bf[nt][h], bf[nt][h + 2]);
                }
        }
    }

    // ---- epilogue: ref chain exactly: f32( bf16(acc) +bf16 bf16(bias) ) ----
    const int nThr = n0 + wn * 64 + (lane & 3) * 2;
#pragma unroll
    for (int t = 0; t < 2; ++t) {
        const int r0 = m0 + wm * 32 + t * 16 + (lane >> 2);
#pragma unroll
        for (int j = 0; j < 8; ++j) {
            const int col = nThr + j * 8;
            const __nv_bfloat16 hb0 = __float2bfloat16(bias[col]);      // exact
            const __nv_bfloat16 hb1 = __float2bfloat16(bias[col + 1]);  // exact
            __nv_bfloat16 h0 = __hadd(__float2bfloat16(acc[t][j][0]), hb0);
            __nv_bfloat16 h1 = __hadd(__float2bfloat16(acc[t][j][1]), hb1);
            __nv_bfloat16 h2 = __hadd(__float2bfloat16(acc[t][j][2]), hb0);
            __nv_bfloat16 h3 = __hadd(__float2bfloat16(acc[t][j][3]), hb1);
            *reinterpret_cast<float2*>(out + (size_t)r0 * N_DIM + col) =
                make_float2(__bfloat162float(h0), __bfloat162float(h1));
            *reinterpret_cast<float2*>(out + (size_t)(r0 + 8) * N_DIM + col) =
                make_float2(__bfloat162float(h2), __bfloat162float(h3));
        }
    }
}

// ---------------- host side ----------------
extern "C" void kernel_launch(void* const* d_in, const int* in_sizes, int n_in,
                              void* d_out, int out_size) {
    // R13-verified order: 0=x(f32), 1=W(f32 quantized), 2=scale(f32), 3=bias(f32)
    const float* xf    = (const float*)d_in[0];
    const float* wf    = (const float*)d_in[1];
    const float* scale = (const float*)d_in[2];
    const float* bias  = (const float*)d_in[3];
    float* out = (float*)d_out;

    void* xptr = nullptr;
    void* wptr = nullptr;
    cudaGetSymbolAddress(&xptr, g_x);
    cudaGetSymbolAddress(&wptr, g_w);

    // 1a: x f32 -> bf16 (64M elems, 8/thread)
    prep_x<<<(int)(((size_t)M_DIM * K_DIM) / (8 * 256)), 256>>>(
        xf, (__nv_bfloat16*)xptr);
    // 1b: W f32 -> bf16 * scale (4M elems, 8/thread)
    prep_w<<<(N_DIM * K_DIM) / (8 * 256), 256>>>(wf, scale, (__nv_bfloat16*)wptr);

    // 2: GEMM, f32 output
    cudaFuncSetAttribute(gemm_kernel,
                         cudaFuncAttributeMaxDynamicSharedMemorySize, SMEM_TOTAL);
    dim3 grid(N_DIM / BN, M_DIM / BM, 1);
    gemm_kernel<<<grid, 256, SMEM_TOTAL>>>((const __nv_bfloat16*)xptr,
                                           (const __nv_bfloat16*)wptr, bias, out);
}